// round 16
// baseline (speedup 1.0000x reference)
#include <cuda_runtime.h>
#include <cuda_fp16.h>
#include <math.h>
#include <stdint.h>

#define NNODES 200000
#define NEDGES 3200000
#define BN_EPS 1e-5f
#define SCAN_BLOCKS ((NNODES + 1023) / 1024)   // 196

// ---------------------------------------------------------------------------
// Static device scratch
// ---------------------------------------------------------------------------
__device__ __half g_b3h[(size_t)NNODES * 40 + 64];      // GEMM3 out (fp16)

__device__ uint32_t g_qx[(size_t)NNODES * 32];          // x int8 [N,128]
__device__ float    g_rsx[NNODES];                       // per-row x scale

__device__ __half g_a1h[(size_t)NNODES * 128 + 16384];  // agg1 out fp16
__device__ __half g_h1h[(size_t)NNODES * 256 + 32768];  // h1 raw fp16 [N,256]
__device__ __half g_a2h[(size_t)NNODES * 256 + 32768];  // agg2 out [N,256]
__device__ __half g_h2h[(size_t)NNODES * 256 + 32768];  // h2 raw fp16 [N,256]

__device__ uint4  g_q8[(size_t)NNODES * 16];            // BNReLU(h1) u8 [N,256]
__device__ float  g_rs[NNODES];                          // per-row quant scale

__device__ __half g_wt1[256 * 128];              // W^T fp16 [N][K]
__device__ __half g_wt2[256 * 256];
__device__ __half g_wt3[64 * 256];               // padded N 40->64

__device__ int   g_cnt[NNODES];
__device__ int   g_cur[NNODES];
__device__ int   g_rowptr[NNODES + 1];
__device__ float g_dinv[NNODES];
__device__ int2  g_edge[NEDGES];                 // (colidx, w bits) packed

__device__ int   g_bsum[256];
__device__ int   g_boff[256];

__device__ double g_sum[512];     // [0:256) layer1, [256:512) layer2
__device__ double g_sumsq[512];
__device__ float  g_scale[256];
__device__ float  g_shift[256];

// ---------------------------------------------------------------------------
// Helpers
// ---------------------------------------------------------------------------
__device__ __forceinline__ void mma_f16(float* c, const uint32_t* a, const uint32_t* b) {
    asm volatile(
        "mma.sync.aligned.m16n8k16.row.col.f32.f16.f16.f32 "
        "{%0,%1,%2,%3}, {%4,%5,%6,%7}, {%8,%9}, {%0,%1,%2,%3};\n"
        : "+f"(c[0]), "+f"(c[1]), "+f"(c[2]), "+f"(c[3])
        : "r"(a[0]), "r"(a[1]), "r"(a[2]), "r"(a[3]), "r"(b[0]), "r"(b[1]));
}

__device__ __forceinline__ void ldsm_x4(uint32_t& r0, uint32_t& r1,
                                        uint32_t& r2, uint32_t& r3, uint32_t addr) {
    asm volatile("ldmatrix.sync.aligned.m8n8.x4.shared.b16 {%0,%1,%2,%3}, [%4];"
                 : "=r"(r0), "=r"(r1), "=r"(r2), "=r"(r3) : "r"(addr));
}

__device__ __forceinline__ void unpack8(uint4 u, float* f) {
    const __half2* p = reinterpret_cast<const __half2*>(&u);
    #pragma unroll
    for (int i = 0; i < 4; i++) {
        float2 t = __half22float2(p[i]);
        f[2 * i] = t.x;
        f[2 * i + 1] = t.y;
    }
}

__device__ __forceinline__ void unpack16u(uint4 u, float* f) {
    #pragma unroll
    for (int i = 0; i < 4; i++) f[i]      = (float)((u.x >> (8 * i)) & 0xFFu);
    #pragma unroll
    for (int i = 0; i < 4; i++) f[4 + i]  = (float)((u.y >> (8 * i)) & 0xFFu);
    #pragma unroll
    for (int i = 0; i < 4; i++) f[8 + i]  = (float)((u.z >> (8 * i)) & 0xFFu);
    #pragma unroll
    for (int i = 0; i < 4; i++) f[12 + i] = (float)((u.w >> (8 * i)) & 0xFFu);
}

// signed int8 unpack (sign-extended)
__device__ __forceinline__ void unpack16s(uint4 u, float* f) {
    #pragma unroll
    for (int i = 0; i < 4; i++)
        f[i]      = (float)((int)(u.x << (24 - 8 * i)) >> 24);
    #pragma unroll
    for (int i = 0; i < 4; i++)
        f[4 + i]  = (float)((int)(u.y << (24 - 8 * i)) >> 24);
    #pragma unroll
    for (int i = 0; i < 4; i++)
        f[8 + i]  = (float)((int)(u.z << (24 - 8 * i)) >> 24);
    #pragma unroll
    for (int i = 0; i < 4; i++)
        f[12 + i] = (float)((int)(u.w << (24 - 8 * i)) >> 24);
}

__device__ __forceinline__ uint4 pack8(const float* f) {
    uint4 u;
    __half2* p = reinterpret_cast<__half2*>(&u);
    #pragma unroll
    for (int i = 0; i < 4; i++)
        p[i] = __floats2half2_rn(f[2 * i], f[2 * i + 1]);
    return u;
}

__device__ __forceinline__ uint32_t smem_u32(const void* p) {
    return (uint32_t)__cvta_generic_to_shared(p);
}

#define CP_ASYNC16(dst_u32, src_ptr, sz) \
    asm volatile("cp.async.cg.shared.global [%0], [%1], 16, %2;" \
                 :: "r"(dst_u32), "l"(src_ptr), "r"(sz))
#define CP_COMMIT() asm volatile("cp.async.commit_group;")
#define CP_WAIT(N)  asm volatile("cp.async.wait_group %0;" :: "n"(N))

__device__ __forceinline__ int warp_incl_scan(int v) {
    #pragma unroll
    for (int o = 1; o < 32; o <<= 1) {
        int n = __shfl_up_sync(0xFFFFFFFFu, v, o);
        if ((threadIdx.x & 31) >= o) v += n;
    }
    return v;
}

// ---------------------------------------------------------------------------
// CSR build
// ---------------------------------------------------------------------------
__global__ void prep_zero_kernel() {
    int i = blockIdx.x * blockDim.x + threadIdx.x;
    if (i < NNODES) { g_cnt[i] = 0; g_cur[i] = 0; }
    if (i < 512) { g_sum[i] = 0.0; g_sumsq[i] = 0.0; }
}

__global__ void count_kernel(const int4* __restrict__ row4) {
    int e4 = blockIdx.x * blockDim.x + threadIdx.x;
    if (e4 >= NEDGES / 4) return;
    int4 r = row4[e4];
    atomicAdd(&g_cnt[r.x], 1);
    atomicAdd(&g_cnt[r.y], 1);
    atomicAdd(&g_cnt[r.z], 1);
    atomicAdd(&g_cnt[r.w], 1);
}

__global__ __launch_bounds__(1024) void scan_block_sums_kernel() {
    __shared__ int sm[32];
    int i = blockIdx.x * 1024 + threadIdx.x;
    int v = 0;
    if (i < NNODES) {
        v = g_cnt[i];
        g_dinv[i] = rsqrtf((float)(v + 1));
    }
    int s = v;
    #pragma unroll
    for (int o = 16; o > 0; o >>= 1) s += __shfl_down_sync(0xFFFFFFFFu, s, o);
    if ((threadIdx.x & 31) == 0) sm[threadIdx.x >> 5] = s;
    __syncthreads();
    if (threadIdx.x < 32) {
        int t = sm[threadIdx.x];
        #pragma unroll
        for (int o = 16; o > 0; o >>= 1) t += __shfl_down_sync(0xFFFFFFFFu, t, o);
        if (threadIdx.x == 0) g_bsum[blockIdx.x] = t;
    }
}

__global__ void scan_bsums_kernel() {
    __shared__ int wsum[8];
    int t = threadIdx.x;
    int v = (t < SCAN_BLOCKS) ? g_bsum[t] : 0;
    int incl = warp_incl_scan(v);
    if ((t & 31) == 31) wsum[t >> 5] = incl;
    __syncthreads();
    if (t < 8) {
        int s = wsum[t];
        #pragma unroll
        for (int o = 1; o < 8; o <<= 1) {
            int n = __shfl_up_sync(0xFFu, s, o);
            if (t >= o) s += n;
        }
        wsum[t] = s;
    }
    __syncthreads();
    int warp = t >> 5;
    if (warp > 0) incl += wsum[warp - 1];
    g_boff[t] = incl - v;
}

__global__ __launch_bounds__(1024) void scan_write_kernel() {
    __shared__ int wsum[32];
    int i = blockIdx.x * 1024 + threadIdx.x;
    int v = (i < NNODES) ? g_cnt[i] : 0;
    int incl = warp_incl_scan(v);
    int lane = threadIdx.x & 31;
    int warp = threadIdx.x >> 5;
    if (lane == 31) wsum[warp] = incl;
    __syncthreads();
    if (threadIdx.x < 32) wsum[threadIdx.x] = warp_incl_scan(wsum[threadIdx.x]);
    __syncthreads();
    if (warp > 0) incl += wsum[warp - 1];
    if (i < NNODES) g_rowptr[i] = g_boff[blockIdx.x] + incl - v;
    if (i == 0) g_rowptr[NNODES] = NEDGES;
}

__global__ void fill_kernel(const int* __restrict__ row, const int* __restrict__ col) {
    int e = blockIdx.x * blockDim.x + threadIdx.x;
    if (e >= NEDGES) return;
    int d = row[e];
    int s = col[e];
    int p = g_rowptr[d] + atomicAdd(&g_cur[d], 1);
    float wv = g_dinv[d] * g_dinv[s];
    g_edge[p] = make_int2(s, __float_as_int(wv));
}

// ---------------------------------------------------------------------------
// x fp32 -> signed int8 with per-row absmax scale.
// block 256 = 8 nodes x 32 lanes; lane owns 4 features (one float4).
// ---------------------------------------------------------------------------
__global__ __launch_bounds__(256) void quantx_kernel(
    const float4* __restrict__ x, uint32_t* __restrict__ qx,
    float* __restrict__ rsx)
{
    int lane = threadIdx.x & 31;
    int node = blockIdx.x * 8 + (threadIdx.x >> 5);   // NNODES % 8 == 0

    float4 v = x[(size_t)node * 32 + lane];
    float mx = fmaxf(fmaxf(fabsf(v.x), fabsf(v.y)), fmaxf(fabsf(v.z), fabsf(v.w)));
    #pragma unroll
    for (int o = 16; o > 0; o >>= 1)
        mx = fmaxf(mx, __shfl_xor_sync(0xFFFFFFFFu, mx, o));

    float inv = (mx > 0.f) ? 127.f / mx : 0.f;
    int q0 = __float2int_rn(v.x * inv);
    int q1 = __float2int_rn(v.y * inv);
    int q2 = __float2int_rn(v.z * inv);
    int q3 = __float2int_rn(v.w * inv);
    uint32_t packed = ((uint32_t)(q0 & 0xFF)) |
                      ((uint32_t)(q1 & 0xFF) << 8) |
                      ((uint32_t)(q2 & 0xFF) << 16) |
                      ((uint32_t)(q3 & 0xFF) << 24);
    qx[(size_t)node * 32 + lane] = packed;
    if (lane == 0) rsx[node] = mx * (1.f / 127.f);
}

__global__ void convert_all_w_kernel(const float* __restrict__ W1,
                                     const float* __restrict__ W2,
                                     const float* __restrict__ W3) {
    int idx = blockIdx.x * blockDim.x + threadIdx.x;
    if (idx < 32768) {
        int n = idx / 128, k = idx % 128;
        g_wt1[idx] = __float2half(W1[(size_t)k * 256 + n]);
    } else if (idx < 98304) {
        int t = idx - 32768;
        int n = t / 256, k = t % 256;
        g_wt2[t] = __float2half(W2[(size_t)k * 256 + n]);
    } else if (idx < 114688) {
        int t = idx - 98304;
        int n = t / 256, k = t % 256;
        g_wt3[t] = (n < 40) ? __float2half(W3[(size_t)k * 40 + n]) : __half(0);
    }
}

// ---------------------------------------------------------------------------
// Quantize BNReLU(h1) -> uint8 with per-node-row scale.
// ---------------------------------------------------------------------------
__global__ __launch_bounds__(256) void quant_kernel(
    const uint4* __restrict__ h, uint2* __restrict__ q8, float* __restrict__ rs)
{
    int lane = threadIdx.x & 31;
    int node = blockIdx.x * 8 + (threadIdx.x >> 5);   // NNODES % 8 == 0

    float4 a0 = *((const float4*)g_scale + lane * 2);
    float4 a1 = *((const float4*)g_scale + lane * 2 + 1);
    float4 b0 = *((const float4*)g_shift + lane * 2);
    float4 b1 = *((const float4*)g_shift + lane * 2 + 1);
    float sc[8] = {a0.x, a0.y, a0.z, a0.w, a1.x, a1.y, a1.z, a1.w};
    float sh[8] = {b0.x, b0.y, b0.z, b0.w, b1.x, b1.y, b1.z, b1.w};

    float v[8];
    unpack8(h[(size_t)node * 32 + lane], v);
    #pragma unroll
    for (int i = 0; i < 8; i++)
        v[i] = fmaxf(fmaf(v[i], sc[i], sh[i]), 0.f);

    float mx = 0.f;
    #pragma unroll
    for (int i = 0; i < 8; i++) mx = fmaxf(mx, v[i]);
    #pragma unroll
    for (int o = 16; o > 0; o >>= 1)
        mx = fmaxf(mx, __shfl_xor_sync(0xFFFFFFFFu, mx, o));

    float inv = (mx > 0.f) ? 255.f / mx : 0.f;
    uint32_t lo = 0, hi = 0;
    #pragma unroll
    for (int i = 0; i < 4; i++) {
        uint32_t q = (uint32_t)__float2int_rn(v[i] * inv);
        lo |= (q > 255u ? 255u : q) << (8 * i);
    }
    #pragma unroll
    for (int i = 0; i < 4; i++) {
        uint32_t q = (uint32_t)__float2int_rn(v[4 + i] * inv);
        hi |= (q > 255u ? 255u : q) << (8 * i);
    }
    q8[(size_t)node * 32 + lane] = make_uint2(lo, hi);
    if (lane == 0) rs[node] = mx * (1.f / 255.f);
}

// ---------------------------------------------------------------------------
// int8 pull aggregation — layer 1. 8 lanes/node, one uint4 (16 features) per
// lane: 8 LDG transactions per gathered 128B row. fp16 output [N,128].
// ---------------------------------------------------------------------------
__global__ __launch_bounds__(256) void agg_s8_kernel(
    const uint4* __restrict__ qx, const float* __restrict__ rsx,
    uint4* __restrict__ out)
{
    int f = threadIdx.x & 7;                            // 0..7
    int node = blockIdx.x * 32 + (threadIdx.x >> 3);    // NNODES % 32 == 0

    int start = g_rowptr[node];
    int end = g_rowptr[node + 1];
    float di = g_dinv[node];
    float ws = di * di * rsx[node];

    float acc0[16], acc1[16];
    {
        float a[16];
        unpack16s(qx[(size_t)node * 8 + f], a);
        #pragma unroll
        for (int i = 0; i < 16; i++) { acc0[i] = a[i] * ws; acc1[i] = 0.f; }
    }

    int e = start;
    for (; e + 4 <= end; e += 4) {
        int2 e0 = g_edge[e + 0], e1 = g_edge[e + 1];
        int2 e2 = g_edge[e + 2], e3 = g_edge[e + 3];
        float wq0 = __int_as_float(e0.y) * rsx[e0.x];
        float wq1 = __int_as_float(e1.y) * rsx[e1.x];
        float wq2 = __int_as_float(e2.y) * rsx[e2.x];
        float wq3 = __int_as_float(e3.y) * rsx[e3.x];
        uint4 u0 = qx[(size_t)e0.x * 8 + f];
        uint4 u1 = qx[(size_t)e1.x * 8 + f];
        uint4 u2 = qx[(size_t)e2.x * 8 + f];
        uint4 u3 = qx[(size_t)e3.x * 8 + f];
        {
            float v[16];
            unpack16s(u0, v);
            #pragma unroll
            for (int i = 0; i < 16; i++) acc0[i] = fmaf(v[i], wq0, acc0[i]);
        }
        {
            float v[16];
            unpack16s(u1, v);
            #pragma unroll
            for (int i = 0; i < 16; i++) acc1[i] = fmaf(v[i], wq1, acc1[i]);
        }
        {
            float v[16];
            unpack16s(u2, v);
            #pragma unroll
            for (int i = 0; i < 16; i++) acc0[i] = fmaf(v[i], wq2, acc0[i]);
        }
        {
            float v[16];
            unpack16s(u3, v);
            #pragma unroll
            for (int i = 0; i < 16; i++) acc1[i] = fmaf(v[i], wq3, acc1[i]);
        }
    }
    for (; e < end; e++) {
        int2 ee = g_edge[e];
        float wq = __int_as_float(ee.y) * rsx[ee.x];
        float v[16];
        unpack16s(qx[(size_t)ee.x * 8 + f], v);
        #pragma unroll
        for (int i = 0; i < 16; i++) acc0[i] = fmaf(v[i], wq, acc0[i]);
    }

    float r[16];
    #pragma unroll
    for (int i = 0; i < 16; i++) r[i] = acc0[i] + acc1[i];
    out[(size_t)node * 16 + f * 2]     = pack8(r);
    out[(size_t)node * 16 + f * 2 + 1] = pack8(r + 8);
}

// ---------------------------------------------------------------------------
// uint8 pull aggregation — layer 2. 16 lanes/node, one uint4 per lane.
// ---------------------------------------------------------------------------
__global__ __launch_bounds__(256) void agg_u8_kernel(
    const uint4* __restrict__ q8, const float* __restrict__ rs,
    uint4* __restrict__ out)
{
    int f = threadIdx.x & 15;                           // 0..15
    int node = blockIdx.x * 16 + (threadIdx.x >> 4);    // NNODES % 16 == 0

    int start = g_rowptr[node];
    int end = g_rowptr[node + 1];
    float di = g_dinv[node];
    float ws = di * di * rs[node];

    float acc0[16], acc1[16];
    {
        float a[16];
        unpack16u(q8[(size_t)node * 16 + f], a);
        #pragma unroll
        for (int i = 0; i < 16; i++) { acc0[i] = a[i] * ws; acc1[i] = 0.f; }
    }

    int e = start;
    for (; e + 4 <= end; e += 4) {
        int2 e0 = g_edge[e + 0], e1 = g_edge[e + 1];
        int2 e2 = g_edge[e + 2], e3 = g_edge[e + 3];
        float wq0 = __int_as_float(e0.y) * rs[e0.x];
        float wq1 = __int_as_float(e1.y) * rs[e1.x];
        float wq2 = __int_as_float(e2.y) * rs[e2.x];
        float wq3 = __int_as_float(e3.y) * rs[e3.x];
        uint4 u0 = q8[(size_t)e0.x * 16 + f];
        uint4 u1 = q8[(size_t)e1.x * 16 + f];
        uint4 u2 = q8[(size_t)e2.x * 16 + f];
        uint4 u3 = q8[(size_t)e3.x * 16 + f];
        {
            float v[16];
            unpack16u(u0, v);
            #pragma unroll
            for (int i = 0; i < 16; i++) acc0[i] = fmaf(v[i], wq0, acc0[i]);
        }
        {
            float v[16];
            unpack16u(u1, v);
            #pragma unroll
            for (int i = 0; i < 16; i++) acc1[i] = fmaf(v[i], wq1, acc1[i]);
        }
        {
            float v[16];
            unpack16u(u2, v);
            #pragma unroll
            for (int i = 0; i < 16; i++) acc0[i] = fmaf(v[i], wq2, acc0[i]);
        }
        {
            float v[16];
            unpack16u(u3, v);
            #pragma unroll
            for (int i = 0; i < 16; i++) acc1[i] = fmaf(v[i], wq3, acc1[i]);
        }
    }
    for (; e < end; e++) {
        int2 ee = g_edge[e];
        float wq = __int_as_float(ee.y) * rs[ee.x];
        float v[16];
        unpack16u(q8[(size_t)ee.x * 16 + f], v);
        #pragma unroll
        for (int i = 0; i < 16; i++) acc0[i] = fmaf(v[i], wq, acc0[i]);
    }

    float r[16];
    #pragma unroll
    for (int i = 0; i < 16; i++) r[i] = acc0[i] + acc1[i];
    out[(size_t)node * 32 + f * 2]     = pack8(r);
    out[(size_t)node * 32 + f * 2 + 1] = pack8(r + 8);
}

// ---------------------------------------------------------------------------
// Layer-3: aggregation over fp16 rows of 40 + fused (+b3, log_softmax).
// ---------------------------------------------------------------------------
__global__ __launch_bounds__(320) void agg_lsm_40_kernel(
    const __half2* __restrict__ h, const float* __restrict__ b3,
    float* __restrict__ out)
{
    __shared__ float red[16][20];
    int f = threadIdx.x % 20;
    int ln = threadIdx.x / 20;
    int node = blockIdx.x * 16 + ln;

    int start = g_rowptr[node];
    int end = g_rowptr[node + 1];
    float di = g_dinv[node];
    float ws = di * di;

    float2 s0 = __half22float2(h[(size_t)node * 20 + f]);
    float ax0 = s0.x * ws, ay0 = s0.y * ws;
    float ax1 = 0.f, ay1 = 0.f, ax2 = 0.f, ay2 = 0.f, ax3 = 0.f, ay3 = 0.f;

    int e = start;
    for (; e + 4 <= end; e += 4) {
        int2 e0 = g_edge[e + 0], e1 = g_edge[e + 1];
        int2 e2 = g_edge[e + 2], e3 = g_edge[e + 3];
        float w0 = __int_as_float(e0.y), w1 = __int_as_float(e1.y);
        float w2 = __int_as_float(e2.y), w3 = __int_as_float(e3.y);
        float2 v0 = __half22float2(h[(size_t)e0.x * 20 + f]);
        float2 v1 = __half22float2(h[(size_t)e1.x * 20 + f]);
        float2 v2 = __half22float2(h[(size_t)e2.x * 20 + f]);
        float2 v3 = __half22float2(h[(size_t)e3.x * 20 + f]);
        ax0 = fmaf(v0.x, w0, ax0); ay0 = fmaf(v0.y, w0, ay0);
        ax1 = fmaf(v1.x, w1, ax1); ay1 = fmaf(v1.y, w1, ay1);
        ax2 = fmaf(v2.x, w2, ax2); ay2 = fmaf(v2.y, w2, ay2);
        ax3 = fmaf(v3.x, w3, ax3); ay3 = fmaf(v3.y, w3, ay3);
    }
    for (; e < end; e++) {
        int2 ee = g_edge[e];
        float w = __int_as_float(ee.y);
        float2 v = __half22float2(h[(size_t)ee.x * 20 + f]);
        ax0 = fmaf(v.x, w, ax0); ay0 = fmaf(v.y, w, ay0);
    }

    float v0 = (ax0 + ax1) + (ax2 + ax3) + b3[f * 2];
    float v1 = (ay0 + ay1) + (ay2 + ay3) + b3[f * 2 + 1];

    red[ln][f] = fmaxf(v0, v1);
    __syncthreads();
    if (f < 4)  red[ln][f] = fmaxf(red[ln][f], red[ln][f + 16]);
    __syncthreads();
    if (f < 8)  red[ln][f] = fmaxf(red[ln][f], red[ln][f + 8]);
    __syncthreads();
    if (f < 4)  red[ln][f] = fmaxf(red[ln][f], red[ln][f + 4]);
    __syncthreads();
    if (f < 2)  red[ln][f] = fmaxf(red[ln][f], red[ln][f + 2]);
    __syncthreads();
    if (f == 0) red[ln][0] = fmaxf(red[ln][0], red[ln][1]);
    __syncthreads();
    float m = red[ln][0];
    __syncthreads();

    float e0 = expf(v0 - m), e1 = expf(v1 - m);
    red[ln][f] = e0 + e1;
    __syncthreads();
    if (f < 4)  red[ln][f] += red[ln][f + 16];
    __syncthreads();
    if (f < 8)  red[ln][f] += red[ln][f + 8];
    __syncthreads();
    if (f < 4)  red[ln][f] += red[ln][f + 4];
    __syncthreads();
    if (f < 2)  red[ln][f] += red[ln][f + 2];
    __syncthreads();
    if (f == 0) red[ln][0] += red[ln][1];
    __syncthreads();
    float lse = m + logf(red[ln][0]);

    *(float2*)(out + (size_t)node * 40 + f * 2) = make_float2(v0 - lse, v1 - lse);
}

// ---------------------------------------------------------------------------
// fp16 tensor-core GEMM (champion form).
// ---------------------------------------------------------------------------
template <int BM, int BN, int BK, bool BNIN, bool BNOUT, bool PIPE, bool HOUT>
__global__ __launch_bounds__(256) void gemm_f16_kernel(
    int M, int K, int Nreal, int statOff,
    const __half* __restrict__ Ah, const __half* __restrict__ Wt, void* Cout)
{
    constexpr int LDA = BK + 8;
    constexpr int LDB = BK + 8;
    constexpr int NSTG = PIPE ? 2 : 1;
    extern __shared__ char smem_raw[];
    __half* As = (__half*)smem_raw;
    __half* Bs = As + NSTG * BM * LDA;

    const int tid = threadIdx.x;
    const int lane = tid & 31;
    const int warp = tid >> 5;
    const int brow = blockIdx.x * BM;
    const int bcol = blockIdx.y * BN;

    constexpr int WTM = BM / 4;
    constexpr int WTN = BN / 2;
    constexpr int MT = WTM / 16;
    constexpr int NT = WTN / 8;
    const int warpRow = (warp & 3) * WTM;
    const int warpCol = (warp >> 2) * WTN;
    const int g = lane >> 2;
    const int t2 = (lane & 3) * 2;

    float c[MT][NT][4] = {};

    constexpr int CHUNKS = BK / 8;
    constexpr int ROWSP = 256 / CHUNKS;
    const int aRow = tid / CHUNKS;
    const int aChunk = (tid % CHUNKS) * 8;

    const int lmA_row = lane & 15;
    const int lmA_k   = (lane >> 4) * 8;
    const int lmB_row = (lane & 7) + ((lane >> 4) * 8);
    const int lmB_k   = ((lane >> 3) & 1) * 8;

    auto load_tile_async = [&](int k0, int stg) {
        __half* Asb = As + stg * BM * LDA;
        __half* Bsb = Bs + stg * BN * LDB;
        #pragma unroll
        for (int r = 0; r < BM; r += ROWSP) {
            int gr = brow + aRow + r;
            int sz = (gr < M) ? 16 : 0;
            const __half* src = Ah + (size_t)(gr < M ? gr : 0) * K + k0 + aChunk;
            CP_ASYNC16(smem_u32(&Asb[(aRow + r) * LDA + aChunk]), src, sz);
        }
        #pragma unroll
        for (int n = 0; n < BN; n += ROWSP) {
            const __half* src = Wt + (size_t)(bcol + aRow + n) * K + k0 + aChunk;
            CP_ASYNC16(smem_u32(&Bsb[(aRow + n) * LDB + aChunk]), src, 16);
        }
    };

    auto load_tile_bnin = [&](int k0) {
        float4 sc0 = *(const float4*)(g_scale + k0 + aChunk);
        float4 sc1 = *(const float4*)(g_scale + k0 + aChunk + 4);
        float4 sh0 = *(const float4*)(g_shift + k0 + aChunk);
        float4 sh1 = *(const float4*)(g_shift + k0 + aChunk + 4);
        float sc[8] = {sc0.x, sc0.y, sc0.z, sc0.w, sc1.x, sc1.y, sc1.z, sc1.w};
        float sh[8] = {sh0.x, sh0.y, sh0.z, sh0.w, sh1.x, sh1.y, sh1.z, sh1.w};
        #pragma unroll
        for (int r = 0; r < BM; r += ROWSP) {
            int gr = brow + aRow + r;
            uint4 u = make_uint4(0, 0, 0, 0);
            if (gr < M) u = *(const uint4*)(Ah + (size_t)gr * K + k0 + aChunk);
            float f[8];
            unpack8(u, f);
            #pragma unroll
            for (int i = 0; i < 8; i++) f[i] = fmaxf(fmaf(f[i], sc[i], sh[i]), 0.f);
            *(uint4*)&As[(aRow + r) * LDA + aChunk] = pack8(f);
        }
        #pragma unroll
        for (int n = 0; n < BN; n += ROWSP) {
            *(uint4*)&Bs[(aRow + n) * LDB + aChunk] =
                *(const uint4*)(Wt + (size_t)(bcol + aRow + n) * K + k0 + aChunk);
        }
    };

    auto compute = [&](int stg) {
        const __half* Asb = As + stg * BM * LDA;
        const __half* Bsb = Bs + stg * BN * LDB;
        const uint32_t aBase = smem_u32(Asb) + ((warpRow + lmA_row) * LDA + lmA_k) * 2;
        const uint32_t bBase = smem_u32(Bsb) + ((warpCol + lmB_row) * LDB + lmB_k) * 2;
        #pragma unroll
        for (int kk = 0; kk < BK / 16; kk++) {
            uint32_t a[MT][4], b[NT][2];
            #pragma unroll
            for (int i = 0; i < MT; i++)
                ldsm_x4(a[i][0], a[i][1], a[i][2], a[i][3],
                        aBase + (i * 16 * LDA + kk * 16) * 2);
            #pragma unroll
            for (int j = 0; j < NT; j += 2)
                ldsm_x4(b[j][0], b[j][1], b[j + 1][0], b[j + 1][1],
                        bBase + (j * 8 * LDB + kk * 16) * 2);
            #pragma unroll
            for (int i = 0; i < MT; i++)
                #pragma unroll
                for (int j = 0; j < NT; j++)
                    mma_f16(c[i][j], a[i], b[j]);
        }
    };

    if (PIPE) {
        int s = 0;
        load_tile_async(0, 0);
        CP_COMMIT();
        for (int k0 = 0; k0 < K; k0 += BK) {
            CP_WAIT(0);
            __syncthreads();
            if (k0 + BK < K) {
                load_tile_async(k0 + BK, s ^ 1);
                CP_COMMIT();
            }
            compute(s);
            s ^= 1;
        }
        __syncthreads();
    } else {
        for (int k0 = 0; k0 < K; k0 += BK) {
            if (BNIN) load_tile_bnin(k0);
            __syncthreads();
            compute(0);
            __syncthreads();
        }
    }

    if (BNOUT) {
        __half* Ch = (__half*)Cout;
        float s[NT * 2] = {}, s2[NT * 2] = {};
        #pragma unroll
        for (int i = 0; i < MT; i++) {
            int r0 = brow + warpRow + i * 16 + g;
            bool v0 = r0 < M, v1 = (r0 + 8) < M;
            #pragma unroll
            for (int j = 0; j < NT; j++) {
                int col = bcol + warpCol + j * 8 + t2;
                if (v0) {
                    *(uint32_t*)(Ch + (size_t)r0 * Nreal + col) =
                        *(uint32_t*)&(__half2_raw)__floats2half2_rn(c[i][j][0], c[i][j][1]);
                    s[j * 2 + 0] += c[i][j][0];  s2[j * 2 + 0] += c[i][j][0] * c[i][j][0];
                    s[j * 2 + 1] += c[i][j][1];  s2[j * 2 + 1] += c[i][j][1] * c[i][j][1];
                }
                if (v1) {
                    *(uint32_t*)(Ch + (size_t)(r0 + 8) * Nreal + col) =
                        *(uint32_t*)&(__half2_raw)__floats2half2_rn(c[i][j][2], c[i][j][3]);
                    s[j * 2 + 0] += c[i][j][2];  s2[j * 2 + 0] += c[i][j][2] * c[i][j][2];
                    s[j * 2 + 1] += c[i][j][3];  s2[j * 2 + 1] += c[i][j][3] * c[i][j][3];
                }
            }
        }
        #pragma unroll
        for (int off = 4; off <= 16; off <<= 1) {
            #pragma unroll
            for (int t = 0; t < NT * 2; t++) {
                s[t]  += __shfl_xor_sync(0xFFFFFFFFu, s[t],  off);
                s2[t] += __shfl_xor_sync(0xFFFFFFFFu, s2[t], off);
            }
        }
        float* ssum  = reinterpret_cast<float*>(As);
        float* ssum2 = ssum + BN;
        __syncthreads();
        if (tid < 2 * BN) ssum[tid] = 0.f;
        __syncthreads();
        if (lane < 4) {
            #pragma unroll
            for (int j = 0; j < NT; j++) {
                #pragma unroll
                for (int hh = 0; hh < 2; hh++) {
                    int cl = warpCol + j * 8 + t2 + hh;
                    atomicAdd(&ssum[cl],  s[j * 2 + hh]);
                    atomicAdd(&ssum2[cl], s2[j * 2 + hh]);
                }
            }
        }
        __syncthreads();
        if (tid < BN) {
            atomicAdd(&g_sum[statOff + bcol + tid],   (double)ssum[tid]);
            atomicAdd(&g_sumsq[statOff + bcol + tid], (double)ssum2[tid]);
        }
    } else if (HOUT) {
        __half* Ch = (__half*)Cout;
        #pragma unroll
        for (int i = 0; i < MT; i++) {
            int r0 = brow + warpRow + i * 16 + g;
            #pragma unroll
            for (int j = 0; j < NT; j++) {
                int col = bcol + warpCol + j * 8 + t2;
                if (col < Nreal) {
                    if (r0 < M)
                        *(uint32_t*)(Ch + (size_t)r0 * Nreal + col) =
                            *(uint32_t*)&(__half2_raw)__floats2half2_rn(c[i][j][0], c[i][j][1]);
                    if (r0 + 8 < M)
                        *(uint32_t*)(Ch + (size_t)(r0 + 8) * Nreal + col) =
                            *(uint32_t*)&(__half2_raw)__floats2half2_rn(c[i][j][2], c[i][j][3]);
                }
            }
        }
    }
}

// ---------------------------------------------------------------------------
// BN finalize
// ---------------------------------------------------------------------------
__global__ void bn_finalize_kernel(const float* __restrict__ gamma,
                                   const float* __restrict__ beta, int statOff) {
    int f = threadIdx.x;
    double mu = g_sum[statOff + f] / (double)NNODES;
    double var = g_sumsq[statOff + f] / (double)NNODES - mu * mu;
    float sc = gamma[f] * rsqrtf((float)var + BN_EPS);
    g_scale[f] = sc;
    g_shift[f] = beta[f] - (float)mu * sc;
}

// ---------------------------------------------------------------------------
// Launch
// ---------------------------------------------------------------------------
extern "C" void kernel_launch(void* const* d_in, const int* in_sizes, int n_in,
                              void* d_out, int out_size) {
    const float* x      = (const float*)d_in[0];
    const int*   ei     = (const int*)d_in[1];
    const float* W1     = (const float*)d_in[2];
    const float* gamma1 = (const float*)d_in[4];
    const float* beta1  = (const float*)d_in[5];
    const float* W2     = (const float*)d_in[6];
    const float* gamma2 = (const float*)d_in[8];
    const float* beta2  = (const float*)d_in[9];
    const float* W3     = (const float*)d_in[10];
    const float* b3     = (const float*)d_in[11];
    float* out = (float*)d_out;

    const int* row = ei;
    const int* col = ei + NEDGES;

    __half *b3h, *a1h, *h1h, *a2h, *h2h, *wt1, *wt2, *wt3;
    uint4* q8;
    float* rs;
    uint32_t* qx;
    float* rsx;
    cudaGetSymbolAddress((void**)&b3h, g_b3h);
    cudaGetSymbolAddress((void**)&a1h, g_a1h);
    cudaGetSymbolAddress((void**)&h1h, g_h1h);
    cudaGetSymbolAddress((void**)&a2h, g_a2h);
    cudaGetSymbolAddress((void**)&h2h, g_h2h);
    cudaGetSymbolAddress((void**)&wt1, g_wt1);
    cudaGetSymbolAddress((void**)&wt2, g_wt2);
    cudaGetSymbolAddress((void**)&wt3, g_wt3);
    cudaGetSymbolAddress((void**)&q8,  g_q8);
    cudaGetSymbolAddress((void**)&rs,  g_rs);
    cudaGetSymbolAddress((void**)&qx,  g_qx);
    cudaGetSymbolAddress((void**)&rsx, g_rsx);

    const int EB = (NEDGES + 255) / 256;
    const int NB = (NNODES + 255) / 256;
    const int GROWS = (NNODES + 127) / 128;   // 1563

    constexpr int SM_PIPE64 = 2 * (128 * 72 + 128 * 72) * 2;   // 73728 B
    constexpr int SM_G3     = (128 * 40 + 64 * 40) * 2;        // 15360 B

    auto gemm12 = gemm_f16_kernel<128, 128, 64, false, true, true, false>;
    auto gemm3  = gemm_f16_kernel<128, 64, 32, true, false, false, true>;
    cudaFuncSetAttribute(gemm12, cudaFuncAttributeMaxDynamicSharedMemorySize, SM_PIPE64);

    // ---- Prep ----
    convert_all_w_kernel<<<(114688 + 255) / 256, 256>>>(W1, W2, W3);
    quantx_kernel<<<NNODES / 8, 256>>>((const float4*)x, qx, rsx);

    // ---- CSR build ----
    prep_zero_kernel<<<NB, 256>>>();
    count_kernel<<<(NEDGES / 4 + 255) / 256, 256>>>((const int4*)row);
    scan_block_sums_kernel<<<SCAN_BLOCKS, 1024>>>();
    scan_bsums_kernel<<<1, 256>>>();
    scan_write_kernel<<<SCAN_BLOCKS, 1024>>>();
    fill_kernel<<<EB, 256>>>(row, col);

    // ---- Layer 1: s8 agg (8 lanes/node) -> GEMM(128->256, fused stats) ----
    agg_s8_kernel<<<NNODES / 32, 256>>>((const uint4*)qx, rsx, (uint4*)a1h);
    gemm12<<<dim3(GROWS, 2), 256, SM_PIPE64>>>(NNODES, 128, 256, 0, a1h, wt1, h1h);
    bn_finalize_kernel<<<1, 256>>>(gamma1, beta1, 0);

    // ---- Layer 2: quant -> u8 agg (16 lanes/node) -> GEMM(256->256, stats) ----
    quant_kernel<<<NNODES / 8, 256>>>((const uint4*)h1h, (uint2*)q8, rs);
    agg_u8_kernel<<<NNODES / 16, 256>>>(q8, rs, (uint4*)a2h);
    gemm12<<<dim3(GROWS, 2), 256, SM_PIPE64>>>(NNODES, 256, 256, 256, a2h, wt2, h2h);
    bn_finalize_kernel<<<1, 256>>>(gamma2, beta2, 256);

    // ---- Layer 3: GEMM(BNReLU in A-load, fp16 out) -> fused agg+log_softmax ----
    gemm3<<<dim3(GROWS, 1), 256, SM_G3>>>(NNODES, 256, 40, 0, h2h, wt3, b3h);
    agg_lsm_40_kernel<<<NNODES / 16, 320>>>((const __half2*)b3h, b3, out);
}

// round 17
// speedup vs baseline: 1.0280x; 1.0280x over previous
#include <cuda_runtime.h>
#include <cuda_fp16.h>
#include <math.h>
#include <stdint.h>

#define NNODES 200000
#define NEDGES 3200000
#define BN_EPS 1e-5f
#define SCAN_BLOCKS ((NNODES + 1023) / 1024)   // 196

// ---------------------------------------------------------------------------
// Static device scratch
// ---------------------------------------------------------------------------
__device__ __half g_b3h[(size_t)NNODES * 40 + 64];      // GEMM3 out (fp16)

__device__ __half g_xh [(size_t)NNODES * 128 + 16384];  // x fp16
__device__ __half g_a1h[(size_t)NNODES * 128 + 16384];  // agg1 out fp16
__device__ __half g_h1h[(size_t)NNODES * 256 + 32768];  // h1 raw fp16 [N,256]
__device__ __half g_a2h[(size_t)NNODES * 256 + 32768];  // agg2 out [N,256]
__device__ __half g_h2h[(size_t)NNODES * 256 + 32768];  // h2 raw fp16 [N,256]

__device__ uint4  g_q8[(size_t)NNODES * 16];            // BNReLU(h1) u8 [N,256]
__device__ float  g_rs[NNODES];                          // per-row quant scale

__device__ __half g_wt1[256 * 128];              // W^T fp16 [N][K]
__device__ __half g_wt2[256 * 256];
__device__ __half g_wt3[64 * 256];               // padded N 40->64

__device__ int   g_cnt[NNODES];
__device__ int   g_cur[NNODES];
__device__ int   g_rowptr[NNODES + 1];
__device__ float g_dinv[NNODES];
__device__ int2  g_edge[NEDGES];                 // (colidx, w bits) packed

__device__ int   g_bsum[256];
__device__ int   g_boff[256];

__device__ double g_sum[512];     // [0:256) layer1, [256:512) layer2
__device__ double g_sumsq[512];
__device__ float  g_scale[256];
__device__ float  g_shift[256];

// ---------------------------------------------------------------------------
// Helpers
// ---------------------------------------------------------------------------
__device__ __forceinline__ void mma_f16(float* c, const uint32_t* a, const uint32_t* b) {
    asm volatile(
        "mma.sync.aligned.m16n8k16.row.col.f32.f16.f16.f32 "
        "{%0,%1,%2,%3}, {%4,%5,%6,%7}, {%8,%9}, {%0,%1,%2,%3};\n"
        : "+f"(c[0]), "+f"(c[1]), "+f"(c[2]), "+f"(c[3])
        : "r"(a[0]), "r"(a[1]), "r"(a[2]), "r"(a[3]), "r"(b[0]), "r"(b[1]));
}

__device__ __forceinline__ void ldsm_x4(uint32_t& r0, uint32_t& r1,
                                        uint32_t& r2, uint32_t& r3, uint32_t addr) {
    asm volatile("ldmatrix.sync.aligned.m8n8.x4.shared.b16 {%0,%1,%2,%3}, [%4];"
                 : "=r"(r0), "=r"(r1), "=r"(r2), "=r"(r3) : "r"(addr));
}

__device__ __forceinline__ void unpack8(uint4 u, float* f) {
    const __half2* p = reinterpret_cast<const __half2*>(&u);
    #pragma unroll
    for (int i = 0; i < 4; i++) {
        float2 t = __half22float2(p[i]);
        f[2 * i] = t.x;
        f[2 * i + 1] = t.y;
    }
}

__device__ __forceinline__ void unpack16u(uint4 u, float* f) {
    #pragma unroll
    for (int i = 0; i < 4; i++) f[i]      = (float)((u.x >> (8 * i)) & 0xFFu);
    #pragma unroll
    for (int i = 0; i < 4; i++) f[4 + i]  = (float)((u.y >> (8 * i)) & 0xFFu);
    #pragma unroll
    for (int i = 0; i < 4; i++) f[8 + i]  = (float)((u.z >> (8 * i)) & 0xFFu);
    #pragma unroll
    for (int i = 0; i < 4; i++) f[12 + i] = (float)((u.w >> (8 * i)) & 0xFFu);
}

__device__ __forceinline__ uint4 pack8(const float* f) {
    uint4 u;
    __half2* p = reinterpret_cast<__half2*>(&u);
    #pragma unroll
    for (int i = 0; i < 4; i++)
        p[i] = __floats2half2_rn(f[2 * i], f[2 * i + 1]);
    return u;
}

__device__ __forceinline__ uint32_t smem_u32(const void* p) {
    return (uint32_t)__cvta_generic_to_shared(p);
}

#define CP_ASYNC16(dst_u32, src_ptr, sz) \
    asm volatile("cp.async.cg.shared.global [%0], [%1], 16, %2;" \
                 :: "r"(dst_u32), "l"(src_ptr), "r"(sz))
#define CP_COMMIT() asm volatile("cp.async.commit_group;")
#define CP_WAIT(N)  asm volatile("cp.async.wait_group %0;" :: "n"(N))

__device__ __forceinline__ int warp_incl_scan(int v) {
    #pragma unroll
    for (int o = 1; o < 32; o <<= 1) {
        int n = __shfl_up_sync(0xFFFFFFFFu, v, o);
        if ((threadIdx.x & 31) >= o) v += n;
    }
    return v;
}

// ---------------------------------------------------------------------------
// CSR build
// ---------------------------------------------------------------------------
__global__ void prep_zero_kernel() {
    int i = blockIdx.x * blockDim.x + threadIdx.x;
    if (i < NNODES) { g_cnt[i] = 0; g_cur[i] = 0; }
    if (i < 512) { g_sum[i] = 0.0; g_sumsq[i] = 0.0; }
}

__global__ void count_kernel(const int4* __restrict__ row4) {
    int e4 = blockIdx.x * blockDim.x + threadIdx.x;
    if (e4 >= NEDGES / 4) return;
    int4 r = row4[e4];
    atomicAdd(&g_cnt[r.x], 1);
    atomicAdd(&g_cnt[r.y], 1);
    atomicAdd(&g_cnt[r.z], 1);
    atomicAdd(&g_cnt[r.w], 1);
}

__global__ __launch_bounds__(1024) void scan_block_sums_kernel() {
    __shared__ int sm[32];
    int i = blockIdx.x * 1024 + threadIdx.x;
    int v = 0;
    if (i < NNODES) {
        v = g_cnt[i];
        g_dinv[i] = rsqrtf((float)(v + 1));
    }
    int s = v;
    #pragma unroll
    for (int o = 16; o > 0; o >>= 1) s += __shfl_down_sync(0xFFFFFFFFu, s, o);
    if ((threadIdx.x & 31) == 0) sm[threadIdx.x >> 5] = s;
    __syncthreads();
    if (threadIdx.x < 32) {
        int t = sm[threadIdx.x];
        #pragma unroll
        for (int o = 16; o > 0; o >>= 1) t += __shfl_down_sync(0xFFFFFFFFu, t, o);
        if (threadIdx.x == 0) g_bsum[blockIdx.x] = t;
    }
}

__global__ void scan_bsums_kernel() {
    __shared__ int wsum[8];
    int t = threadIdx.x;
    int v = (t < SCAN_BLOCKS) ? g_bsum[t] : 0;
    int incl = warp_incl_scan(v);
    if ((t & 31) == 31) wsum[t >> 5] = incl;
    __syncthreads();
    if (t < 8) {
        int s = wsum[t];
        #pragma unroll
        for (int o = 1; o < 8; o <<= 1) {
            int n = __shfl_up_sync(0xFFu, s, o);
            if (t >= o) s += n;
        }
        wsum[t] = s;
    }
    __syncthreads();
    int warp = t >> 5;
    if (warp > 0) incl += wsum[warp - 1];
    g_boff[t] = incl - v;
}

__global__ __launch_bounds__(1024) void scan_write_kernel() {
    __shared__ int wsum[32];
    int i = blockIdx.x * 1024 + threadIdx.x;
    int v = (i < NNODES) ? g_cnt[i] : 0;
    int incl = warp_incl_scan(v);
    int lane = threadIdx.x & 31;
    int warp = threadIdx.x >> 5;
    if (lane == 31) wsum[warp] = incl;
    __syncthreads();
    if (threadIdx.x < 32) wsum[threadIdx.x] = warp_incl_scan(wsum[threadIdx.x]);
    __syncthreads();
    if (warp > 0) incl += wsum[warp - 1];
    if (i < NNODES) g_rowptr[i] = g_boff[blockIdx.x] + incl - v;
    if (i == 0) g_rowptr[NNODES] = NEDGES;
}

__global__ void fill_kernel(const int* __restrict__ row, const int* __restrict__ col) {
    int e = blockIdx.x * blockDim.x + threadIdx.x;
    if (e >= NEDGES) return;
    int d = row[e];
    int s = col[e];
    int p = g_rowptr[d] + atomicAdd(&g_cur[d], 1);
    float wv = g_dinv[d] * g_dinv[s];
    g_edge[p] = make_int2(s, __float_as_int(wv));
}

// ---------------------------------------------------------------------------
// x fp32 -> fp16; all-weights transpose (merged single launch)
// ---------------------------------------------------------------------------
__global__ void f32_to_f16_kernel(const float4* __restrict__ in,
                                  uint2* __restrict__ out, size_t n4) {
    size_t idx = (size_t)blockIdx.x * blockDim.x + threadIdx.x;
    if (idx >= n4) return;
    float4 v = in[idx];
    uint2 r;
    *reinterpret_cast<__half2*>(&r.x) = __floats2half2_rn(v.x, v.y);
    *reinterpret_cast<__half2*>(&r.y) = __floats2half2_rn(v.z, v.w);
    out[idx] = r;
}

__global__ void convert_all_w_kernel(const float* __restrict__ W1,
                                     const float* __restrict__ W2,
                                     const float* __restrict__ W3) {
    int idx = blockIdx.x * blockDim.x + threadIdx.x;
    if (idx < 32768) {
        int n = idx / 128, k = idx % 128;
        g_wt1[idx] = __float2half(W1[(size_t)k * 256 + n]);
    } else if (idx < 98304) {
        int t = idx - 32768;
        int n = t / 256, k = t % 256;
        g_wt2[t] = __float2half(W2[(size_t)k * 256 + n]);
    } else if (idx < 114688) {
        int t = idx - 98304;
        int n = t / 256, k = t % 256;
        g_wt3[t] = (n < 40) ? __float2half(W3[(size_t)k * 40 + n]) : __half(0);
    }
}

// ---------------------------------------------------------------------------
// Quantize BNReLU(h1) -> uint8 with per-node-row scale.
// ---------------------------------------------------------------------------
__global__ __launch_bounds__(256) void quant_kernel(
    const uint4* __restrict__ h, uint2* __restrict__ q8, float* __restrict__ rs)
{
    int lane = threadIdx.x & 31;
    int node = blockIdx.x * 8 + (threadIdx.x >> 5);   // NNODES % 8 == 0

    float4 a0 = *((const float4*)g_scale + lane * 2);
    float4 a1 = *((const float4*)g_scale + lane * 2 + 1);
    float4 b0 = *((const float4*)g_shift + lane * 2);
    float4 b1 = *((const float4*)g_shift + lane * 2 + 1);
    float sc[8] = {a0.x, a0.y, a0.z, a0.w, a1.x, a1.y, a1.z, a1.w};
    float sh[8] = {b0.x, b0.y, b0.z, b0.w, b1.x, b1.y, b1.z, b1.w};

    float v[8];
    unpack8(h[(size_t)node * 32 + lane], v);
    #pragma unroll
    for (int i = 0; i < 8; i++)
        v[i] = fmaxf(fmaf(v[i], sc[i], sh[i]), 0.f);

    float mx = 0.f;
    #pragma unroll
    for (int i = 0; i < 8; i++) mx = fmaxf(mx, v[i]);
    #pragma unroll
    for (int o = 16; o > 0; o >>= 1)
        mx = fmaxf(mx, __shfl_xor_sync(0xFFFFFFFFu, mx, o));

    float inv = (mx > 0.f) ? 255.f / mx : 0.f;
    uint32_t lo = 0, hi = 0;
    #pragma unroll
    for (int i = 0; i < 4; i++) {
        uint32_t q = (uint32_t)__float2int_rn(v[i] * inv);
        lo |= (q > 255u ? 255u : q) << (8 * i);
    }
    #pragma unroll
    for (int i = 0; i < 4; i++) {
        uint32_t q = (uint32_t)__float2int_rn(v[4 + i] * inv);
        hi |= (q > 255u ? 255u : q) << (8 * i);
    }
    q8[(size_t)node * 32 + lane] = make_uint2(lo, hi);
    if (lane == 0) rs[node] = mx * (1.f / 255.f);
}

// ---------------------------------------------------------------------------
// fp16 pull aggregation (known-good shape) — layer 1 (no BN).
// ---------------------------------------------------------------------------
template <int F8, int NPB>
__global__ __launch_bounds__(F8 * NPB) void agg_f16_kernel(
    const uint4* __restrict__ h, uint4* __restrict__ out)
{
    int f = threadIdx.x % F8;
    int node = blockIdx.x * NPB + threadIdx.x / F8;
    if (node >= NNODES) return;

    int start = g_rowptr[node];
    int end = g_rowptr[node + 1];
    float di = g_dinv[node];
    float ws = di * di;

    float a[8], acc0[8], acc1[8];
    unpack8(h[(size_t)node * F8 + f], a);
    #pragma unroll
    for (int i = 0; i < 8; i++) { acc0[i] = a[i] * ws; acc1[i] = 0.f; }

    int e = start;
    for (; e + 4 <= end; e += 4) {
        int2 e0 = g_edge[e + 0], e1 = g_edge[e + 1];
        int2 e2 = g_edge[e + 2], e3 = g_edge[e + 3];
        float w0 = __int_as_float(e0.y), w1 = __int_as_float(e1.y);
        float w2 = __int_as_float(e2.y), w3 = __int_as_float(e3.y);
        uint4 u0 = h[(size_t)e0.x * F8 + f];
        uint4 u1 = h[(size_t)e1.x * F8 + f];
        uint4 u2 = h[(size_t)e2.x * F8 + f];
        uint4 u3 = h[(size_t)e3.x * F8 + f];
        float v0[8], v1[8], v2[8], v3[8];
        unpack8(u0, v0); unpack8(u1, v1); unpack8(u2, v2); unpack8(u3, v3);
        #pragma unroll
        for (int i = 0; i < 8; i++) {
            acc0[i] = fmaf(v0[i], w0, acc0[i]);
            acc1[i] = fmaf(v1[i], w1, acc1[i]);
            acc0[i] = fmaf(v2[i], w2, acc0[i]);
            acc1[i] = fmaf(v3[i], w3, acc1[i]);
        }
    }
    for (; e < end; e++) {
        int2 ee = g_edge[e];
        float w = __int_as_float(ee.y);
        float v[8];
        unpack8(h[(size_t)ee.x * F8 + f], v);
        #pragma unroll
        for (int i = 0; i < 8; i++) acc0[i] = fmaf(v[i], w, acc0[i]);
    }

    float r[8];
    #pragma unroll
    for (int i = 0; i < 8; i++) r[i] = acc0[i] + acc1[i];
    out[(size_t)node * F8 + f] = pack8(r);
}

// ---------------------------------------------------------------------------
// uint8 pull aggregation — layer 2. 16 lanes/node, one uint4 per lane.
// ---------------------------------------------------------------------------
__global__ __launch_bounds__(256) void agg_u8_kernel(
    const uint4* __restrict__ q8, const float* __restrict__ rs,
    uint4* __restrict__ out)
{
    int f = threadIdx.x & 15;                           // 0..15
    int node = blockIdx.x * 16 + (threadIdx.x >> 4);    // NNODES % 16 == 0

    int start = g_rowptr[node];
    int end = g_rowptr[node + 1];
    float di = g_dinv[node];
    float ws = di * di * rs[node];

    float acc0[16], acc1[16];
    {
        float a[16];
        unpack16u(q8[(size_t)node * 16 + f], a);
        #pragma unroll
        for (int i = 0; i < 16; i++) { acc0[i] = a[i] * ws; acc1[i] = 0.f; }
    }

    int e = start;
    for (; e + 4 <= end; e += 4) {
        int2 e0 = g_edge[e + 0], e1 = g_edge[e + 1];
        int2 e2 = g_edge[e + 2], e3 = g_edge[e + 3];
        float wq0 = __int_as_float(e0.y) * rs[e0.x];
        float wq1 = __int_as_float(e1.y) * rs[e1.x];
        float wq2 = __int_as_float(e2.y) * rs[e2.x];
        float wq3 = __int_as_float(e3.y) * rs[e3.x];
        uint4 u0 = q8[(size_t)e0.x * 16 + f];
        uint4 u1 = q8[(size_t)e1.x * 16 + f];
        uint4 u2 = q8[(size_t)e2.x * 16 + f];
        uint4 u3 = q8[(size_t)e3.x * 16 + f];
        {
            float v[16];
            unpack16u(u0, v);
            #pragma unroll
            for (int i = 0; i < 16; i++) acc0[i] = fmaf(v[i], wq0, acc0[i]);
        }
        {
            float v[16];
            unpack16u(u1, v);
            #pragma unroll
            for (int i = 0; i < 16; i++) acc1[i] = fmaf(v[i], wq1, acc1[i]);
        }
        {
            float v[16];
            unpack16u(u2, v);
            #pragma unroll
            for (int i = 0; i < 16; i++) acc0[i] = fmaf(v[i], wq2, acc0[i]);
        }
        {
            float v[16];
            unpack16u(u3, v);
            #pragma unroll
            for (int i = 0; i < 16; i++) acc1[i] = fmaf(v[i], wq3, acc1[i]);
        }
    }
    for (; e < end; e++) {
        int2 ee = g_edge[e];
        float wq = __int_as_float(ee.y) * rs[ee.x];
        float v[16];
        unpack16u(q8[(size_t)ee.x * 16 + f], v);
        #pragma unroll
        for (int i = 0; i < 16; i++) acc0[i] = fmaf(v[i], wq, acc0[i]);
    }

    float r[16];
    #pragma unroll
    for (int i = 0; i < 16; i++) r[i] = acc0[i] + acc1[i];
    out[(size_t)node * 32 + f * 2]     = pack8(r);
    out[(size_t)node * 32 + f * 2 + 1] = pack8(r + 8);
}

// ---------------------------------------------------------------------------
// Layer-3: agg over fp16 rows of 40 + fused (+b3, log_softmax).
// 5 lanes/node x uint4 (8 features, 16B): 5 LDG transactions per 80B row.
// 320 threads = 64 nodes/block; smem reduce over 5 lanes.
// ---------------------------------------------------------------------------
__global__ __launch_bounds__(320) void agg_lsm_40_kernel(
    const uint4* __restrict__ h, const float* __restrict__ b3,
    float* __restrict__ out)
{
    __shared__ float redm[64][5];
    __shared__ float reds[64][5];
    int f = threadIdx.x % 5;
    int ln = threadIdx.x / 5;                 // 0..63
    int node = blockIdx.x * 64 + ln;          // NNODES % 64 == 0 (200000/64=3125)

    int start = g_rowptr[node];
    int end = g_rowptr[node + 1];
    float di = g_dinv[node];
    float ws = di * di;

    float acc0[8], acc1[8];
    {
        float a[8];
        unpack8(h[(size_t)node * 5 + f], a);
        #pragma unroll
        for (int i = 0; i < 8; i++) { acc0[i] = a[i] * ws; acc1[i] = 0.f; }
    }

    int e = start;
    for (; e + 4 <= end; e += 4) {
        int2 e0 = g_edge[e + 0], e1 = g_edge[e + 1];
        int2 e2 = g_edge[e + 2], e3 = g_edge[e + 3];
        float w0 = __int_as_float(e0.y), w1 = __int_as_float(e1.y);
        float w2 = __int_as_float(e2.y), w3 = __int_as_float(e3.y);
        uint4 u0 = h[(size_t)e0.x * 5 + f];
        uint4 u1 = h[(size_t)e1.x * 5 + f];
        uint4 u2 = h[(size_t)e2.x * 5 + f];
        uint4 u3 = h[(size_t)e3.x * 5 + f];
        float v0[8], v1[8], v2[8], v3[8];
        unpack8(u0, v0); unpack8(u1, v1); unpack8(u2, v2); unpack8(u3, v3);
        #pragma unroll
        for (int i = 0; i < 8; i++) {
            acc0[i] = fmaf(v0[i], w0, acc0[i]);
            acc1[i] = fmaf(v1[i], w1, acc1[i]);
            acc0[i] = fmaf(v2[i], w2, acc0[i]);
            acc1[i] = fmaf(v3[i], w3, acc1[i]);
        }
    }
    for (; e < end; e++) {
        int2 ee = g_edge[e];
        float w = __int_as_float(ee.y);
        float v[8];
        unpack8(h[(size_t)ee.x * 5 + f], v);
        #pragma unroll
        for (int i = 0; i < 8; i++) acc0[i] = fmaf(v[i], w, acc0[i]);
    }

    float4 bb0 = *(const float4*)(b3 + f * 8);
    float4 bb1 = *(const float4*)(b3 + f * 8 + 4);
    float bv[8] = {bb0.x, bb0.y, bb0.z, bb0.w, bb1.x, bb1.y, bb1.z, bb1.w};

    float v[8];
    #pragma unroll
    for (int i = 0; i < 8; i++) v[i] = acc0[i] + acc1[i] + bv[i];

    // ---- max over 40 values (8 local, 5 lanes) ----
    float m8 = v[0];
    #pragma unroll
    for (int i = 1; i < 8; i++) m8 = fmaxf(m8, v[i]);
    redm[ln][f] = m8;
    __syncthreads();
    float m = fmaxf(fmaxf(fmaxf(redm[ln][0], redm[ln][1]),
                          fmaxf(redm[ln][2], redm[ln][3])), redm[ln][4]);

    // ---- sum of exp ----
    float s8 = 0.f;
    float ev[8];
    #pragma unroll
    for (int i = 0; i < 8; i++) { ev[i] = expf(v[i] - m); s8 += ev[i]; }
    reds[ln][f] = s8;
    __syncthreads();
    float ssum = ((reds[ln][0] + reds[ln][1]) + (reds[ln][2] + reds[ln][3])) + reds[ln][4];
    float lse = m + logf(ssum);

    float* dst = out + (size_t)node * 40 + f * 8;
    *(float4*)dst = make_float4(v[0] - lse, v[1] - lse, v[2] - lse, v[3] - lse);
    *(float4*)(dst + 4) = make_float4(v[4] - lse, v[5] - lse, v[6] - lse, v[7] - lse);
}

// ---------------------------------------------------------------------------
// fp16 tensor-core GEMM (champion form).
// ---------------------------------------------------------------------------
template <int BM, int BN, int BK, bool BNIN, bool BNOUT, bool PIPE, bool HOUT>
__global__ __launch_bounds__(256) void gemm_f16_kernel(
    int M, int K, int Nreal, int statOff,
    const __half* __restrict__ Ah, const __half* __restrict__ Wt, void* Cout)
{
    constexpr int LDA = BK + 8;
    constexpr int LDB = BK + 8;
    constexpr int NSTG = PIPE ? 2 : 1;
    extern __shared__ char smem_raw[];
    __half* As = (__half*)smem_raw;
    __half* Bs = As + NSTG * BM * LDA;

    const int tid = threadIdx.x;
    const int lane = tid & 31;
    const int warp = tid >> 5;
    const int brow = blockIdx.x * BM;
    const int bcol = blockIdx.y * BN;

    constexpr int WTM = BM / 4;
    constexpr int WTN = BN / 2;
    constexpr int MT = WTM / 16;
    constexpr int NT = WTN / 8;
    const int warpRow = (warp & 3) * WTM;
    const int warpCol = (warp >> 2) * WTN;
    const int g = lane >> 2;
    const int t2 = (lane & 3) * 2;

    float c[MT][NT][4] = {};

    constexpr int CHUNKS = BK / 8;
    constexpr int ROWSP = 256 / CHUNKS;
    const int aRow = tid / CHUNKS;
    const int aChunk = (tid % CHUNKS) * 8;

    const int lmA_row = lane & 15;
    const int lmA_k   = (lane >> 4) * 8;
    const int lmB_row = (lane & 7) + ((lane >> 4) * 8);
    const int lmB_k   = ((lane >> 3) & 1) * 8;

    auto load_tile_async = [&](int k0, int stg) {
        __half* Asb = As + stg * BM * LDA;
        __half* Bsb = Bs + stg * BN * LDB;
        #pragma unroll
        for (int r = 0; r < BM; r += ROWSP) {
            int gr = brow + aRow + r;
            int sz = (gr < M) ? 16 : 0;
            const __half* src = Ah + (size_t)(gr < M ? gr : 0) * K + k0 + aChunk;
            CP_ASYNC16(smem_u32(&Asb[(aRow + r) * LDA + aChunk]), src, sz);
        }
        #pragma unroll
        for (int n = 0; n < BN; n += ROWSP) {
            const __half* src = Wt + (size_t)(bcol + aRow + n) * K + k0 + aChunk;
            CP_ASYNC16(smem_u32(&Bsb[(aRow + n) * LDB + aChunk]), src, 16);
        }
    };

    auto load_tile_bnin = [&](int k0) {
        float4 sc0 = *(const float4*)(g_scale + k0 + aChunk);
        float4 sc1 = *(const float4*)(g_scale + k0 + aChunk + 4);
        float4 sh0 = *(const float4*)(g_shift + k0 + aChunk);
        float4 sh1 = *(const float4*)(g_shift + k0 + aChunk + 4);
        float sc[8] = {sc0.x, sc0.y, sc0.z, sc0.w, sc1.x, sc1.y, sc1.z, sc1.w};
        float sh[8] = {sh0.x, sh0.y, sh0.z, sh0.w, sh1.x, sh1.y, sh1.z, sh1.w};
        #pragma unroll
        for (int r = 0; r < BM; r += ROWSP) {
            int gr = brow + aRow + r;
            uint4 u = make_uint4(0, 0, 0, 0);
            if (gr < M) u = *(const uint4*)(Ah + (size_t)gr * K + k0 + aChunk);
            float f[8];
            unpack8(u, f);
            #pragma unroll
            for (int i = 0; i < 8; i++) f[i] = fmaxf(fmaf(f[i], sc[i], sh[i]), 0.f);
            *(uint4*)&As[(aRow + r) * LDA + aChunk] = pack8(f);
        }
        #pragma unroll
        for (int n = 0; n < BN; n += ROWSP) {
            *(uint4*)&Bs[(aRow + n) * LDB + aChunk] =
                *(const uint4*)(Wt + (size_t)(bcol + aRow + n) * K + k0 + aChunk);
        }
    };

    auto compute = [&](int stg) {
        const __half* Asb = As + stg * BM * LDA;
        const __half* Bsb = Bs + stg * BN * LDB;
        const uint32_t aBase = smem_u32(Asb) + ((warpRow + lmA_row) * LDA + lmA_k) * 2;
        const uint32_t bBase = smem_u32(Bsb) + ((warpCol + lmB_row) * LDB + lmB_k) * 2;
        #pragma unroll
        for (int kk = 0; kk < BK / 16; kk++) {
            uint32_t a[MT][4], b[NT][2];
            #pragma unroll
            for (int i = 0; i < MT; i++)
                ldsm_x4(a[i][0], a[i][1], a[i][2], a[i][3],
                        aBase + (i * 16 * LDA + kk * 16) * 2);
            #pragma unroll
            for (int j = 0; j < NT; j += 2)
                ldsm_x4(b[j][0], b[j][1], b[j + 1][0], b[j + 1][1],
                        bBase + (j * 8 * LDB + kk * 16) * 2);
            #pragma unroll
            for (int i = 0; i < MT; i++)
                #pragma unroll
                for (int j = 0; j < NT; j++)
                    mma_f16(c[i][j], a[i], b[j]);
        }
    };

    if (PIPE) {
        int s = 0;
        load_tile_async(0, 0);
        CP_COMMIT();
        for (int k0 = 0; k0 < K; k0 += BK) {
            CP_WAIT(0);
            __syncthreads();
            if (k0 + BK < K) {
                load_tile_async(k0 + BK, s ^ 1);
                CP_COMMIT();
            }
            compute(s);
            s ^= 1;
        }
        __syncthreads();
    } else {
        for (int k0 = 0; k0 < K; k0 += BK) {
            if (BNIN) load_tile_bnin(k0);
            __syncthreads();
            compute(0);
            __syncthreads();
        }
    }

    if (BNOUT) {
        __half* Ch = (__half*)Cout;
        float s[NT * 2] = {}, s2[NT * 2] = {};
        #pragma unroll
        for (int i = 0; i < MT; i++) {
            int r0 = brow + warpRow + i * 16 + g;
            bool v0 = r0 < M, v1 = (r0 + 8) < M;
            #pragma unroll
            for (int j = 0; j < NT; j++) {
                int col = bcol + warpCol + j * 8 + t2;
                if (v0) {
                    *(uint32_t*)(Ch + (size_t)r0 * Nreal + col) =
                        *(uint32_t*)&(__half2_raw)__floats2half2_rn(c[i][j][0], c[i][j][1]);
                    s[j * 2 + 0] += c[i][j][0];  s2[j * 2 + 0] += c[i][j][0] * c[i][j][0];
                    s[j * 2 + 1] += c[i][j][1];  s2[j * 2 + 1] += c[i][j][1] * c[i][j][1];
                }
                if (v1) {
                    *(uint32_t*)(Ch + (size_t)(r0 + 8) * Nreal + col) =
                        *(uint32_t*)&(__half2_raw)__floats2half2_rn(c[i][j][2], c[i][j][3]);
                    s[j * 2 + 0] += c[i][j][2];  s2[j * 2 + 0] += c[i][j][2] * c[i][j][2];
                    s[j * 2 + 1] += c[i][j][3];  s2[j * 2 + 1] += c[i][j][3] * c[i][j][3];
                }
            }
        }
        #pragma unroll
        for (int off = 4; off <= 16; off <<= 1) {
            #pragma unroll
            for (int t = 0; t < NT * 2; t++) {
                s[t]  += __shfl_xor_sync(0xFFFFFFFFu, s[t],  off);
                s2[t] += __shfl_xor_sync(0xFFFFFFFFu, s2[t], off);
            }
        }
        float* ssum  = reinterpret_cast<float*>(As);
        float* ssum2 = ssum + BN;
        __syncthreads();
        if (tid < 2 * BN) ssum[tid] = 0.f;
        __syncthreads();
        if (lane < 4) {
            #pragma unroll
            for (int j = 0; j < NT; j++) {
                #pragma unroll
                for (int hh = 0; hh < 2; hh++) {
                    int cl = warpCol + j * 8 + t2 + hh;
                    atomicAdd(&ssum[cl],  s[j * 2 + hh]);
                    atomicAdd(&ssum2[cl], s2[j * 2 + hh]);
                }
            }
        }
        __syncthreads();
        if (tid < BN) {
            atomicAdd(&g_sum[statOff + bcol + tid],   (double)ssum[tid]);
            atomicAdd(&g_sumsq[statOff + bcol + tid], (double)ssum2[tid]);
        }
    } else if (HOUT) {
        __half* Ch = (__half*)Cout;
        #pragma unroll
        for (int i = 0; i < MT; i++) {
            int r0 = brow + warpRow + i * 16 + g;
            #pragma unroll
            for (int j = 0; j < NT; j++) {
                int col = bcol + warpCol + j * 8 + t2;
                if (col < Nreal) {
                    if (r0 < M)
                        *(uint32_t*)(Ch + (size_t)r0 * Nreal + col) =
                            *(uint32_t*)&(__half2_raw)__floats2half2_rn(c[i][j][0], c[i][j][1]);
                    if (r0 + 8 < M)
                        *(uint32_t*)(Ch + (size_t)(r0 + 8) * Nreal + col) =
                            *(uint32_t*)&(__half2_raw)__floats2half2_rn(c[i][j][2], c[i][j][3]);
                }
            }
        }
    }
}

// ---------------------------------------------------------------------------
// BN finalize
// ---------------------------------------------------------------------------
__global__ void bn_finalize_kernel(const float* __restrict__ gamma,
                                   const float* __restrict__ beta, int statOff) {
    int f = threadIdx.x;
    double mu = g_sum[statOff + f] / (double)NNODES;
    double var = g_sumsq[statOff + f] / (double)NNODES - mu * mu;
    float sc = gamma[f] * rsqrtf((float)var + BN_EPS);
    g_scale[f] = sc;
    g_shift[f] = beta[f] - (float)mu * sc;
}

// ---------------------------------------------------------------------------
// Launch
// ---------------------------------------------------------------------------
extern "C" void kernel_launch(void* const* d_in, const int* in_sizes, int n_in,
                              void* d_out, int out_size) {
    const float* x      = (const float*)d_in[0];
    const int*   ei     = (const int*)d_in[1];
    const float* W1     = (const float*)d_in[2];
    const float* gamma1 = (const float*)d_in[4];
    const float* beta1  = (const float*)d_in[5];
    const float* W2     = (const float*)d_in[6];
    const float* gamma2 = (const float*)d_in[8];
    const float* beta2  = (const float*)d_in[9];
    const float* W3     = (const float*)d_in[10];
    const float* b3     = (const float*)d_in[11];
    float* out = (float*)d_out;

    const int* row = ei;
    const int* col = ei + NEDGES;

    __half *b3h, *xh, *a1h, *h1h, *a2h, *h2h, *wt1, *wt2, *wt3;
    uint4* q8;
    float* rs;
    cudaGetSymbolAddress((void**)&b3h, g_b3h);
    cudaGetSymbolAddress((void**)&xh,  g_xh);
    cudaGetSymbolAddress((void**)&a1h, g_a1h);
    cudaGetSymbolAddress((void**)&h1h, g_h1h);
    cudaGetSymbolAddress((void**)&a2h, g_a2h);
    cudaGetSymbolAddress((void**)&h2h, g_h2h);
    cudaGetSymbolAddress((void**)&wt1, g_wt1);
    cudaGetSymbolAddress((void**)&wt2, g_wt2);
    cudaGetSymbolAddress((void**)&wt3, g_wt3);
    cudaGetSymbolAddress((void**)&q8,  g_q8);
    cudaGetSymbolAddress((void**)&rs,  g_rs);

    const int EB = (NEDGES + 255) / 256;
    const int NB = (NNODES + 255) / 256;
    const int GROWS = (NNODES + 127) / 128;   // 1563

    constexpr int SM_PIPE64 = 2 * (128 * 72 + 128 * 72) * 2;   // 73728 B
    constexpr int SM_G3     = (128 * 40 + 64 * 40) * 2;        // 15360 B

    auto gemm12 = gemm_f16_kernel<128, 128, 64, false, true, true, false>;
    auto gemm3  = gemm_f16_kernel<128, 64, 32, true, false, false, true>;
    cudaFuncSetAttribute(gemm12, cudaFuncAttributeMaxDynamicSharedMemorySize, SM_PIPE64);

    // ---- Prep ----
    convert_all_w_kernel<<<(114688 + 255) / 256, 256>>>(W1, W2, W3);
    {
        size_t n4 = (size_t)NNODES * 128 / 4;
        f32_to_f16_kernel<<<(int)((n4 + 255) / 256), 256>>>(
            (const float4*)x, (uint2*)xh, n4);
    }

    // ---- CSR build ----
    prep_zero_kernel<<<NB, 256>>>();
    count_kernel<<<(NEDGES / 4 + 255) / 256, 256>>>((const int4*)row);
    scan_block_sums_kernel<<<SCAN_BLOCKS, 1024>>>();
    scan_bsums_kernel<<<1, 256>>>();
    scan_write_kernel<<<SCAN_BLOCKS, 1024>>>();
    fill_kernel<<<EB, 256>>>(row, col);

    // ---- Layer 1: fp16 agg -> GEMM(128->256, fp16 out + fused BN stats) ----
    agg_f16_kernel<16, 16><<<NNODES / 16, 256>>>((const uint4*)xh, (uint4*)a1h);
    gemm12<<<dim3(GROWS, 2), 256, SM_PIPE64>>>(NNODES, 128, 256, 0, a1h, wt1, h1h);
    bn_finalize_kernel<<<1, 256>>>(gamma1, beta1, 0);

    // ---- Layer 2: quant -> u8 agg (16 lanes/node) -> GEMM(256->256, stats) ----
    quant_kernel<<<NNODES / 8, 256>>>((const uint4*)h1h, (uint2*)q8, rs);
    agg_u8_kernel<<<NNODES / 16, 256>>>(q8, rs, (uint4*)a2h);
    gemm12<<<dim3(GROWS, 2), 256, SM_PIPE64>>>(NNODES, 256, 256, 256, a2h, wt2, h2h);
    bn_finalize_kernel<<<1, 256>>>(gamma2, beta2, 256);

    // ---- Layer 3: GEMM(BNReLU in A-load, fp16 out) -> fused agg+log_softmax ----
    gemm3<<<dim3(GROWS, 1), 256, SM_G3>>>(NNODES, 256, 40, 0, h2h, wt3, b3h);
    agg_lsm_40_kernel<<<NNODES / 64, 320>>>((const uint4*)b3h, b3, out);
}